// round 1
// baseline (speedup 1.0000x reference)
#include <cuda_runtime.h>
#include <cuda_bf16.h>

// Problem constants
#define S  4096
#define D  512
#define H  8
#define DK 64
#define FF 2048
#define EPS 1e-6f

// ---------------- scratch (device globals; no allocation allowed) ----------------
__device__ float g_h   [S * D];   // LN1 output
__device__ float g_q   [S * D];
__device__ float g_k   [S * D];
__device__ float g_v   [S * D];
__device__ float g_attn[S * D];   // attention output (pre O-proj)
__device__ float g_x1  [S * D];   // x + attn@wo + bo
__device__ float g_h2  [S * D];   // LN2 output
__device__ float g_ff  [S * FF];  // relu(h2@w1+b1)

// ---------------- block reduction helper ----------------
__device__ __forceinline__ float block_sum(float v) {
    __shared__ float sh[8];
    #pragma unroll
    for (int o = 16; o > 0; o >>= 1) v += __shfl_xor_sync(0xffffffffu, v, o);
    if ((threadIdx.x & 31) == 0) sh[threadIdx.x >> 5] = v;
    __syncthreads();
    float r;
    if (threadIdx.x < 32) {
        float t = (threadIdx.x < 8) ? sh[threadIdx.x] : 0.f;
        #pragma unroll
        for (int o = 4; o > 0; o >>= 1) t += __shfl_xor_sync(0xffffffffu, t, o);
        if (threadIdx.x == 0) sh[0] = t;
    }
    __syncthreads();
    r = sh[0];
    __syncthreads();   // safe for next reuse of sh
    return r;
}

// ---------------- LayerNorm (torch.std semantics: Bessel, eps on std) ----------------
__global__ __launch_bounds__(256) void ln_kernel(
    const float* __restrict__ x, float* __restrict__ y,
    const float* __restrict__ alpha, const float* __restrict__ beta)
{
    int row = blockIdx.x;
    const float* xr = x + (size_t)row * D;
    float s = 0.f;
    for (int i = threadIdx.x; i < D; i += 256) s += xr[i];
    float mean = block_sum(s) * (1.0f / D);

    float sq = 0.f;
    for (int i = threadIdx.x; i < D; i += 256) {
        float d = xr[i] - mean;
        sq += d * d;
    }
    float var = block_sum(sq) * (1.0f / (D - 1));   // Bessel-corrected
    float stdv = sqrtf(var);
    float a = alpha[0], b = beta[0];
    float inv = a / (stdv + EPS);
    float* yr = y + (size_t)row * D;
    for (int i = threadIdx.x; i < D; i += 256)
        yr[i] = (xr[i] - mean) * inv + b;
}

// ---------------- generic tiled GEMM: C = A[M,K] @ W[K,N] + bias (+relu / +residual) ----
// EPI: 0 = bias only, 1 = bias+relu, 2 = bias+residual
#define BM 64
#define BN 64
#define BKT 16

template<int EPI>
__global__ __launch_bounds__(256) void gemm_kernel(
    const float* __restrict__ A, const float* __restrict__ W,
    const float* __restrict__ bias, const float* __restrict__ R,
    float* __restrict__ C, int M, int N, int K)
{
    __shared__ float As[BKT][BM + 1];
    __shared__ float Ws[BKT][BN];

    int bm = blockIdx.y * BM;
    int bn = blockIdx.x * BN;
    int tid = threadIdx.x;
    int tx = tid & 15;
    int ty = tid >> 4;

    float acc[4][4];
    #pragma unroll
    for (int i = 0; i < 4; i++)
        #pragma unroll
        for (int j = 0; j < 4; j++) acc[i][j] = 0.f;

    for (int k0 = 0; k0 < K; k0 += BKT) {
        // load A tile (64x16), transposed into smem
        #pragma unroll
        for (int i = 0; i < 4; i++) {
            int m = (tid >> 4) + 16 * i;
            As[tid & 15][m] = A[(size_t)(bm + m) * K + k0 + (tid & 15)];
        }
        // load W tile (16x64)
        #pragma unroll
        for (int i = 0; i < 4; i++) {
            int kk = (tid >> 6) + 4 * i;
            Ws[kk][tid & 63] = W[(size_t)(k0 + kk) * N + bn + (tid & 63)];
        }
        __syncthreads();

        #pragma unroll
        for (int kk = 0; kk < BKT; kk++) {
            float a[4], b[4];
            #pragma unroll
            for (int i = 0; i < 4; i++) a[i] = As[kk][ty + 16 * i];
            #pragma unroll
            for (int j = 0; j < 4; j++) b[j] = Ws[kk][tx + 16 * j];
            #pragma unroll
            for (int i = 0; i < 4; i++)
                #pragma unroll
                for (int j = 0; j < 4; j++)
                    acc[i][j] += a[i] * b[j];
        }
        __syncthreads();
    }

    #pragma unroll
    for (int i = 0; i < 4; i++) {
        int m = bm + ty + 16 * i;
        #pragma unroll
        for (int j = 0; j < 4; j++) {
            int n = bn + tx + 16 * j;
            float v = acc[i][j] + bias[n];
            if (EPI == 1) v = fmaxf(v, 0.f);
            if (EPI == 2) v += R[(size_t)m * N + n];
            C[(size_t)m * N + n] = v;
        }
    }
}

// ---------------- flash attention (fp32, online softmax) ----------------
// Grid: (S/32, H). Block: 256 threads. Each block: 32 query rows of one head.
// Thread t owns query row r = t>>3 and output cols {cg + 8*jj}, cg = t&7.
#define BQ 32
#define BKEY 64

__global__ __launch_bounds__(256) void attn_kernel(
    const float* __restrict__ Q, const float* __restrict__ K,
    const float* __restrict__ V, const int* __restrict__ mask,
    float* __restrict__ O)
{
    extern __shared__ float smem[];
    float (*Qs)[DK]       = (float (*)[DK])      smem;                    // 32x64
    float (*Kt)[DK + 1]   = (float (*)[DK + 1])(smem + BQ * DK);          // 64x65
    float (*Vt)[DK]       = (float (*)[DK])     (smem + BQ * DK + BKEY * (DK + 1)); // 64x64
    float (*Ss)[BKEY]     = (float (*)[BKEY])   (smem + BQ * DK + BKEY * (DK + 1) + BKEY * DK); // 32x64

    int h    = blockIdx.y;
    int q0   = blockIdx.x * BQ;
    int hoff = h * DK;
    int tid  = threadIdx.x;
    int r    = tid >> 3;   // 0..31
    int cg   = tid & 7;    // 0..7

    // load Q tile
    for (int i = tid; i < BQ * DK; i += 256) {
        int rr = i >> 6, dd = i & 63;
        Qs[rr][dd] = Q[(size_t)(q0 + rr) * D + hoff + dd];
    }
    __syncthreads();

    float m = -1e30f, l = 0.f;
    float acc[8];
    #pragma unroll
    for (int j = 0; j < 8; j++) acc[j] = 0.f;

    for (int kt = 0; kt < S; kt += BKEY) {
        // load K, V tiles
        for (int i = tid; i < BKEY * DK; i += 256) {
            int rr = i >> 6, dd = i & 63;
            Kt[rr][dd] = K[(size_t)(kt + rr) * D + hoff + dd];
            Vt[rr][dd] = V[(size_t)(kt + rr) * D + hoff + dd];
        }
        __syncthreads();

        // scores: thread computes 8 entries of its row
        float sc[8];
        #pragma unroll
        for (int jj = 0; jj < 8; jj++) {
            int c = cg + 8 * jj;
            float s = 0.f;
            #pragma unroll
            for (int d = 0; d < DK; d++) s += Qs[r][d] * Kt[c][d];
            s *= 0.125f;                                  // 1/sqrt(64)
            if (mask[kt + c] == 0) s = -1e9f;
            sc[jj] = s;
        }

        // row max (reduce across the 8 threads of this row)
        float tm = sc[0];
        #pragma unroll
        for (int jj = 1; jj < 8; jj++) tm = fmaxf(tm, sc[jj]);
        #pragma unroll
        for (int o = 4; o > 0; o >>= 1) tm = fmaxf(tm, __shfl_xor_sync(0xffffffffu, tm, o, 8));

        float newm  = fmaxf(m, tm);
        float scale = __expf(m - newm);

        float psum = 0.f;
        #pragma unroll
        for (int jj = 0; jj < 8; jj++) {
            float p = __expf(sc[jj] - newm);
            Ss[r][cg + 8 * jj] = p;
            psum += p;
        }
        #pragma unroll
        for (int o = 4; o > 0; o >>= 1) psum += __shfl_xor_sync(0xffffffffu, psum, o, 8);
        l = l * scale + psum;
        m = newm;
        __syncwarp();   // P row visible within warp (row owned by one warp)

        // AV accumulate
        #pragma unroll
        for (int jj = 0; jj < 8; jj++) acc[jj] *= scale;
        #pragma unroll 4
        for (int kk = 0; kk < BKEY; kk++) {
            float p = Ss[r][kk];
            #pragma unroll
            for (int jj = 0; jj < 8; jj++)
                acc[jj] += p * Vt[kk][cg + 8 * jj];
        }
        __syncthreads();  // before K/V reload
    }

    float inv = 1.f / l;
    #pragma unroll
    for (int jj = 0; jj < 8; jj++)
        O[(size_t)(q0 + r) * D + hoff + cg + 8 * jj] = acc[jj] * inv;
}

// ---------------- launch ----------------
static const int ATTN_SMEM = (BQ * DK + BKEY * (DK + 1) + BKEY * DK + BQ * BKEY) * (int)sizeof(float); // 49408 B

extern "C" void kernel_launch(void* const* d_in, const int* in_sizes, int n_in,
                              void* d_out, int out_size)
{
    const float* x    = (const float*)d_in[0];
    const int*   mask = (const int*)  d_in[1];
    const float* wq   = (const float*)d_in[2];
    const float* bq   = (const float*)d_in[3];
    const float* wk   = (const float*)d_in[4];
    const float* bk   = (const float*)d_in[5];
    const float* wv   = (const float*)d_in[6];
    const float* bv   = (const float*)d_in[7];
    const float* wo   = (const float*)d_in[8];
    const float* bo   = (const float*)d_in[9];
    const float* w1   = (const float*)d_in[10];
    const float* b1   = (const float*)d_in[11];
    const float* w2   = (const float*)d_in[12];
    const float* b2   = (const float*)d_in[13];
    const float* ln1a = (const float*)d_in[14];
    const float* ln1b = (const float*)d_in[15];
    const float* ln2a = (const float*)d_in[16];
    const float* ln2b = (const float*)d_in[17];
    float* out = (float*)d_out;

    float *h, *q, *k, *v, *attn, *x1, *h2, *ff;
    cudaGetSymbolAddress((void**)&h,    g_h);
    cudaGetSymbolAddress((void**)&q,    g_q);
    cudaGetSymbolAddress((void**)&k,    g_k);
    cudaGetSymbolAddress((void**)&v,    g_v);
    cudaGetSymbolAddress((void**)&attn, g_attn);
    cudaGetSymbolAddress((void**)&x1,   g_x1);
    cudaGetSymbolAddress((void**)&h2,   g_h2);
    cudaGetSymbolAddress((void**)&ff,   g_ff);

    cudaFuncSetAttribute(attn_kernel, cudaFuncAttributeMaxDynamicSharedMemorySize, ATTN_SMEM);

    // LN1
    ln_kernel<<<S, 256>>>(x, h, ln1a, ln1b);

    // QKV projections
    dim3 gD(D / BN, S / BM);      // (8, 64)
    gemm_kernel<0><<<gD, 256>>>(h, wq, bq, nullptr, q, S, D, D);
    gemm_kernel<0><<<gD, 256>>>(h, wk, bk, nullptr, k, S, D, D);
    gemm_kernel<0><<<gD, 256>>>(h, wv, bv, nullptr, v, S, D, D);

    // attention
    attn_kernel<<<dim3(S / BQ, H), 256, ATTN_SMEM>>>(q, k, v, mask, attn);

    // output projection + residual
    gemm_kernel<2><<<gD, 256>>>(attn, wo, bo, x, x1, S, D, D);

    // LN2
    ln_kernel<<<S, 256>>>(x1, h2, ln2a, ln2b);

    // FFN
    dim3 gFF(FF / BN, S / BM);    // (32, 64)
    gemm_kernel<1><<<gFF, 256>>>(h2, w1, b1, nullptr, ff, S, FF, D);
    gemm_kernel<2><<<gD, 256>>>(ff, w2, b2, x1, out, S, D, FF);
}

// round 2
// speedup vs baseline: 5.1139x; 5.1139x over previous
#include <cuda_runtime.h>
#include <cuda_bf16.h>
#include <cstdint>

// Problem constants
#define S  4096
#define D  512
#define H  8
#define DK 64
#define FF 2048
#define EPS 1e-6f

// ---------------- scratch (device globals; no allocation allowed) ----------------
__device__ float g_h   [S * D];   // LN1 output
__device__ float g_q   [S * D];
__device__ float g_k   [S * D];
__device__ float g_v   [S * D];
__device__ float g_attn[S * D];   // attention output (pre O-proj)
__device__ float g_x1  [S * D];   // x + attn@wo + bo
__device__ float g_h2  [S * D];   // LN2 output
__device__ float g_ff  [S * FF];  // relu(h2@w1+b1)

// ---------------- helpers ----------------
__device__ __forceinline__ uint32_t f2tf(float f) {
    uint32_t r;
    asm("cvt.rna.tf32.f32 %0, %1;" : "=r"(r) : "f"(f));
    return r;
}

__device__ __forceinline__ void mma_tf32(float* c, const uint32_t* a, uint32_t b0, uint32_t b1) {
    asm volatile(
        "mma.sync.aligned.m16n8k8.row.col.f32.tf32.tf32.f32 "
        "{%0,%1,%2,%3},{%4,%5,%6,%7},{%8,%9},{%0,%1,%2,%3};"
        : "+f"(c[0]), "+f"(c[1]), "+f"(c[2]), "+f"(c[3])
        : "r"(a[0]), "r"(a[1]), "r"(a[2]), "r"(a[3]), "r"(b0), "r"(b1));
}

__device__ __forceinline__ float block_sum(float v) {
    __shared__ float sh[8];
    #pragma unroll
    for (int o = 16; o > 0; o >>= 1) v += __shfl_xor_sync(0xffffffffu, v, o);
    if ((threadIdx.x & 31) == 0) sh[threadIdx.x >> 5] = v;
    __syncthreads();
    if (threadIdx.x < 32) {
        float t = (threadIdx.x < 8) ? sh[threadIdx.x] : 0.f;
        #pragma unroll
        for (int o = 4; o > 0; o >>= 1) t += __shfl_xor_sync(0xffffffffu, t, o);
        if (threadIdx.x == 0) sh[0] = t;
    }
    __syncthreads();
    float r = sh[0];
    __syncthreads();
    return r;
}

// ---------------- LayerNorm (torch.std semantics: Bessel, eps on std) ----------------
__global__ __launch_bounds__(256) void ln_kernel(
    const float* __restrict__ x, float* __restrict__ y,
    const float* __restrict__ alpha, const float* __restrict__ beta)
{
    int row = blockIdx.x;
    const float* xr = x + (size_t)row * D;
    float s = 0.f;
    for (int i = threadIdx.x; i < D; i += 256) s += xr[i];
    float mean = block_sum(s) * (1.0f / D);

    float sq = 0.f;
    for (int i = threadIdx.x; i < D; i += 256) {
        float d = xr[i] - mean;
        sq += d * d;
    }
    float var = block_sum(sq) * (1.0f / (D - 1));   // Bessel-corrected
    float stdv = sqrtf(var);
    float a = alpha[0], b = beta[0];
    float inv = a / (stdv + EPS);
    float* yr = y + (size_t)row * D;
    for (int i = threadIdx.x; i < D; i += 256)
        yr[i] = (xr[i] - mean) * inv + b;
}

// ---------------- TF32 mma GEMM: C = A[M,K] @ W[K,N] + bias (+relu / +residual) ----
// EPI: 0 = bias only, 1 = bias+relu, 2 = bias+residual
#define GBM 128
#define GBN 128
#define GBK 32
#define ASTR 36     // 36 % 32 == 4 -> conflict-free a-frag reads
#define WSTR 136    // 136 % 32 == 8 -> conflict-free b-frag reads

template<int EPI>
__global__ __launch_bounds__(256) void mma_gemm(
    const float* __restrict__ A, const float* __restrict__ W,
    const float* __restrict__ bias, const float* __restrict__ R,
    float* __restrict__ C, int M, int N, int K)
{
    __shared__ uint32_t As[GBM * ASTR];   // 18432 B
    __shared__ uint32_t Ws[GBK * WSTR];   // 17408 B

    int tid  = threadIdx.x;
    int warp = tid >> 5, lane = tid & 31;
    int warp_m = warp >> 1;   // 0..3
    int warp_n = warp & 1;    // 0..1
    int g = lane >> 2;        // group id (0..7)
    int t = lane & 3;         // thread-in-group (0..3)

    int bm = blockIdx.y * GBM;
    int bn = blockIdx.x * GBN;

    float acc[2][8][4];
    #pragma unroll
    for (int mi = 0; mi < 2; mi++)
        #pragma unroll
        for (int ni = 0; ni < 8; ni++)
            #pragma unroll
            for (int r = 0; r < 4; r++) acc[mi][ni][r] = 0.f;

    for (int k0 = 0; k0 < K; k0 += GBK) {
        // stage A tile (128x32) -> tf32 smem
        #pragma unroll
        for (int it = 0; it < 4; it++) {
            int slot = tid + it * 256;
            int row = slot >> 3, sc = (slot & 7) * 4;
            float4 v = *(const float4*)&A[(size_t)(bm + row) * K + k0 + sc];
            uint4 u = { f2tf(v.x), f2tf(v.y), f2tf(v.z), f2tf(v.w) };
            *(uint4*)&As[row * ASTR + sc] = u;
        }
        // stage W tile (32x128) -> tf32 smem
        #pragma unroll
        for (int it = 0; it < 4; it++) {
            int slot = tid + it * 256;
            int row = slot >> 5, sc = (slot & 31) * 4;
            float4 v = *(const float4*)&W[(size_t)(k0 + row) * N + bn + sc];
            uint4 u = { f2tf(v.x), f2tf(v.y), f2tf(v.z), f2tf(v.w) };
            *(uint4*)&Ws[row * WSTR + sc] = u;
        }
        __syncthreads();

        #pragma unroll
        for (int kk = 0; kk < GBK; kk += 8) {
            uint32_t a[2][4];
            #pragma unroll
            for (int mi = 0; mi < 2; mi++) {
                int mrow = warp_m * 32 + mi * 16;
                a[mi][0] = As[(mrow + g)     * ASTR + kk + t];
                a[mi][1] = As[(mrow + 8 + g) * ASTR + kk + t];
                a[mi][2] = As[(mrow + g)     * ASTR + kk + 4 + t];
                a[mi][3] = As[(mrow + 8 + g) * ASTR + kk + 4 + t];
            }
            #pragma unroll
            for (int ni = 0; ni < 8; ni++) {
                int nc = warp_n * 64 + ni * 8;
                uint32_t b0 = Ws[(kk + t)     * WSTR + nc + g];
                uint32_t b1 = Ws[(kk + 4 + t) * WSTR + nc + g];
                #pragma unroll
                for (int mi = 0; mi < 2; mi++)
                    mma_tf32(acc[mi][ni], a[mi], b0, b1);
            }
        }
        __syncthreads();
    }

    // epilogue
    #pragma unroll
    for (int mi = 0; mi < 2; mi++) {
        int row0 = bm + warp_m * 32 + mi * 16 + g;
        #pragma unroll
        for (int ni = 0; ni < 8; ni++) {
            int col0 = bn + warp_n * 64 + ni * 8 + 2 * t;
            float b0 = bias[col0], b1 = bias[col0 + 1];

            float v0 = acc[mi][ni][0] + b0;
            float v1 = acc[mi][ni][1] + b1;
            float v2 = acc[mi][ni][2] + b0;
            float v3 = acc[mi][ni][3] + b1;
            if (EPI == 1) {
                v0 = fmaxf(v0, 0.f); v1 = fmaxf(v1, 0.f);
                v2 = fmaxf(v2, 0.f); v3 = fmaxf(v3, 0.f);
            }
            if (EPI == 2) {
                float2 r0 = *(const float2*)&R[(size_t)row0 * N + col0];
                float2 r1 = *(const float2*)&R[(size_t)(row0 + 8) * N + col0];
                v0 += r0.x; v1 += r0.y; v2 += r1.x; v3 += r1.y;
            }
            *(float2*)&C[(size_t)row0 * N + col0]       = make_float2(v0, v1);
            *(float2*)&C[(size_t)(row0 + 8) * N + col0] = make_float2(v2, v3);
        }
    }
}

// ---------------- TF32 mma flash attention ----------------
// Grid (S/64, H), 128 threads (4 warps). Each warp owns 16 query rows.
#define ABQ 64
#define ABK 64
#define QSTR 68   // %32==4 -> conflict-free a-frag
#define KSTR 68   // %32==4 -> conflict-free (key,d) b-frag reads
#define VSTR 72   // %32==8 -> conflict-free (k,d) b-frag reads
#define PSTR 68

#define SM_Q 0
#define SM_K (SM_Q + ABQ * QSTR)
#define SM_V (SM_K + ABK * KSTR)
#define SM_P (SM_V + ABK * VSTR)
#define SM_MSK (SM_P + 4 * 16 * PSTR)
#define ATTN_SMEM_WORDS (SM_MSK + ABK)

__global__ __launch_bounds__(128) void mma_attn(
    const float* __restrict__ Q, const float* __restrict__ K,
    const float* __restrict__ V, const int* __restrict__ mask,
    float* __restrict__ O)
{
    extern __shared__ uint32_t sm[];
    uint32_t* Qs = sm + SM_Q;
    uint32_t* Ks = sm + SM_K;
    uint32_t* Vs = sm + SM_V;
    uint32_t* Ps = sm + SM_P;
    int*      Ms = (int*)(sm + SM_MSK);

    int tid  = threadIdx.x;
    int warp = tid >> 5, lane = tid & 31;
    int g = lane >> 2, t = lane & 3;

    int hoff = blockIdx.y * DK;
    int q0   = blockIdx.x * ABQ;
    int wrow = warp * 16;               // warp's row base within tile

    // load Q tile (64 x 64), convert to tf32
    #pragma unroll
    for (int it = 0; it < 8; it++) {
        int slot = tid + it * 128;
        int row = slot >> 4, sc = (slot & 15) * 4;
        float4 v = *(const float4*)&Q[(size_t)(q0 + row) * D + hoff + sc];
        uint4 u = { f2tf(v.x), f2tf(v.y), f2tf(v.z), f2tf(v.w) };
        *(uint4*)&Qs[row * QSTR + sc] = u;
    }

    float m_lo = -1e30f, m_hi = -1e30f;
    float l_lo = 0.f,    l_hi = 0.f;
    float o_[8][4];
    #pragma unroll
    for (int ni = 0; ni < 8; ni++)
        #pragma unroll
        for (int r = 0; r < 4; r++) o_[ni][r] = 0.f;

    uint32_t* Pw = Ps + warp * 16 * PSTR;

    for (int kt = 0; kt < S; kt += ABK) {
        // load K, V tiles + mask slice
        #pragma unroll
        for (int it = 0; it < 8; it++) {
            int slot = tid + it * 128;
            int row = slot >> 4, sc = (slot & 15) * 4;
            float4 kv = *(const float4*)&K[(size_t)(kt + row) * D + hoff + sc];
            uint4 uk = { f2tf(kv.x), f2tf(kv.y), f2tf(kv.z), f2tf(kv.w) };
            *(uint4*)&Ks[row * KSTR + sc] = uk;
            float4 vv = *(const float4*)&V[(size_t)(kt + row) * D + hoff + sc];
            uint4 uv = { f2tf(vv.x), f2tf(vv.y), f2tf(vv.z), f2tf(vv.w) };
            *(uint4*)&Vs[row * VSTR + sc] = uv;
        }
        if (tid < ABK) Ms[tid] = mask[kt + tid];
        __syncthreads();

        // scores = Q @ K^T  (per warp: 16 rows x 64 keys)
        float sc_[8][4];
        #pragma unroll
        for (int ni = 0; ni < 8; ni++)
            #pragma unroll
            for (int r = 0; r < 4; r++) sc_[ni][r] = 0.f;

        #pragma unroll
        for (int kk = 0; kk < DK; kk += 8) {
            uint32_t a[4];
            a[0] = Qs[(wrow + g)     * QSTR + kk + t];
            a[1] = Qs[(wrow + 8 + g) * QSTR + kk + t];
            a[2] = Qs[(wrow + g)     * QSTR + kk + 4 + t];
            a[3] = Qs[(wrow + 8 + g) * QSTR + kk + 4 + t];
            #pragma unroll
            for (int ni = 0; ni < 8; ni++) {
                uint32_t b0 = Ks[(ni * 8 + g) * KSTR + kk + t];
                uint32_t b1 = Ks[(ni * 8 + g) * KSTR + kk + 4 + t];
                mma_tf32(sc_[ni], a, b0, b1);
            }
        }

        // scale + mask
        #pragma unroll
        for (int ni = 0; ni < 8; ni++) {
            int col = ni * 8 + 2 * t;
            int mk0 = Ms[col], mk1 = Ms[col + 1];
            sc_[ni][0] = (mk0 == 0) ? -1e9f : sc_[ni][0] * 0.125f;
            sc_[ni][1] = (mk1 == 0) ? -1e9f : sc_[ni][1] * 0.125f;
            sc_[ni][2] = (mk0 == 0) ? -1e9f : sc_[ni][2] * 0.125f;
            sc_[ni][3] = (mk1 == 0) ? -1e9f : sc_[ni][3] * 0.125f;
        }

        // row maxes (rows g and g+8), reduce across 4 threads of the group
        float tm_lo = -1e30f, tm_hi = -1e30f;
        #pragma unroll
        for (int ni = 0; ni < 8; ni++) {
            tm_lo = fmaxf(tm_lo, fmaxf(sc_[ni][0], sc_[ni][1]));
            tm_hi = fmaxf(tm_hi, fmaxf(sc_[ni][2], sc_[ni][3]));
        }
        tm_lo = fmaxf(tm_lo, __shfl_xor_sync(0xffffffffu, tm_lo, 1));
        tm_lo = fmaxf(tm_lo, __shfl_xor_sync(0xffffffffu, tm_lo, 2));
        tm_hi = fmaxf(tm_hi, __shfl_xor_sync(0xffffffffu, tm_hi, 1));
        tm_hi = fmaxf(tm_hi, __shfl_xor_sync(0xffffffffu, tm_hi, 2));

        float nm_lo = fmaxf(m_lo, tm_lo);
        float nm_hi = fmaxf(m_hi, tm_hi);
        float scl_lo = __expf(m_lo - nm_lo);
        float scl_hi = __expf(m_hi - nm_hi);
        m_lo = nm_lo; m_hi = nm_hi;

        // p = exp(s - m), write to per-warp P, accumulate row sums
        float rs_lo = 0.f, rs_hi = 0.f;
        #pragma unroll
        for (int ni = 0; ni < 8; ni++) {
            int col = ni * 8 + 2 * t;
            float p0 = __expf(sc_[ni][0] - m_lo);
            float p1 = __expf(sc_[ni][1] - m_lo);
            float p2 = __expf(sc_[ni][2] - m_hi);
            float p3 = __expf(sc_[ni][3] - m_hi);
            rs_lo += p0 + p1;
            rs_hi += p2 + p3;
            Pw[g * PSTR + col]           = f2tf(p0);
            Pw[g * PSTR + col + 1]       = f2tf(p1);
            Pw[(g + 8) * PSTR + col]     = f2tf(p2);
            Pw[(g + 8) * PSTR + col + 1] = f2tf(p3);
        }
        rs_lo += __shfl_xor_sync(0xffffffffu, rs_lo, 1);
        rs_lo += __shfl_xor_sync(0xffffffffu, rs_lo, 2);
        rs_hi += __shfl_xor_sync(0xffffffffu, rs_hi, 1);
        rs_hi += __shfl_xor_sync(0xffffffffu, rs_hi, 2);
        l_lo = l_lo * scl_lo + rs_lo;
        l_hi = l_hi * scl_hi + rs_hi;

        // rescale O accumulators
        #pragma unroll
        for (int ni = 0; ni < 8; ni++) {
            o_[ni][0] *= scl_lo; o_[ni][1] *= scl_lo;
            o_[ni][2] *= scl_hi; o_[ni][3] *= scl_hi;
        }
        __syncwarp();

        // O += P @ V
        #pragma unroll
        for (int kk = 0; kk < ABK; kk += 8) {
            uint32_t a[4];
            a[0] = Pw[g * PSTR + kk + t];
            a[1] = Pw[(8 + g) * PSTR + kk + t];
            a[2] = Pw[g * PSTR + kk + 4 + t];
            a[3] = Pw[(8 + g) * PSTR + kk + 4 + t];
            #pragma unroll
            for (int ni = 0; ni < 8; ni++) {
                uint32_t b0 = Vs[(kk + t)     * VSTR + ni * 8 + g];
                uint32_t b1 = Vs[(kk + 4 + t) * VSTR + ni * 8 + g];
                mma_tf32(o_[ni], a, b0, b1);
            }
        }
        __syncthreads();  // before next tile overwrite
    }

    float inv_lo = 1.f / l_lo;
    float inv_hi = 1.f / l_hi;
    int row_lo = q0 + wrow + g;
    int row_hi = row_lo + 8;
    #pragma unroll
    for (int ni = 0; ni < 8; ni++) {
        int col = hoff + ni * 8 + 2 * t;
        *(float2*)&O[(size_t)row_lo * D + col] =
            make_float2(o_[ni][0] * inv_lo, o_[ni][1] * inv_lo);
        *(float2*)&O[(size_t)row_hi * D + col] =
            make_float2(o_[ni][2] * inv_hi, o_[ni][3] * inv_hi);
    }
}

// ---------------- launch ----------------
extern "C" void kernel_launch(void* const* d_in, const int* in_sizes, int n_in,
                              void* d_out, int out_size)
{
    const float* x    = (const float*)d_in[0];
    const int*   mask = (const int*)  d_in[1];
    const float* wq   = (const float*)d_in[2];
    const float* bq   = (const float*)d_in[3];
    const float* wk   = (const float*)d_in[4];
    const float* bk   = (const float*)d_in[5];
    const float* wv   = (const float*)d_in[6];
    const float* bv   = (const float*)d_in[7];
    const float* wo   = (const float*)d_in[8];
    const float* bo   = (const float*)d_in[9];
    const float* w1   = (const float*)d_in[10];
    const float* b1   = (const float*)d_in[11];
    const float* w2   = (const float*)d_in[12];
    const float* b2   = (const float*)d_in[13];
    const float* ln1a = (const float*)d_in[14];
    const float* ln1b = (const float*)d_in[15];
    const float* ln2a = (const float*)d_in[16];
    const float* ln2b = (const float*)d_in[17];
    float* out = (float*)d_out;

    float *h, *q, *k, *v, *attn, *x1, *h2, *ff;
    cudaGetSymbolAddress((void**)&h,    g_h);
    cudaGetSymbolAddress((void**)&q,    g_q);
    cudaGetSymbolAddress((void**)&k,    g_k);
    cudaGetSymbolAddress((void**)&v,    g_v);
    cudaGetSymbolAddress((void**)&attn, g_attn);
    cudaGetSymbolAddress((void**)&x1,   g_x1);
    cudaGetSymbolAddress((void**)&h2,   g_h2);
    cudaGetSymbolAddress((void**)&ff,   g_ff);

    static bool configured = false;
    if (!configured) {
        cudaFuncSetAttribute(mma_attn, cudaFuncAttributeMaxDynamicSharedMemorySize,
                             ATTN_SMEM_WORDS * (int)sizeof(uint32_t));
        configured = true;
    }

    // LN1
    ln_kernel<<<S, 256>>>(x, h, ln1a, ln1b);

    // QKV projections
    dim3 gD(D / GBN, S / GBM);      // (4, 32)
    mma_gemm<0><<<gD, 256>>>(h, wq, bq, nullptr, q, S, D, D);
    mma_gemm<0><<<gD, 256>>>(h, wk, bk, nullptr, k, S, D, D);
    mma_gemm<0><<<gD, 256>>>(h, wv, bv, nullptr, v, S, D, D);

    // attention
    mma_attn<<<dim3(S / ABQ, H), 128, ATTN_SMEM_WORDS * sizeof(uint32_t)>>>(q, k, v, mask, attn);

    // output projection + residual
    mma_gemm<2><<<gD, 256>>>(attn, wo, bo, x, x1, S, D, D);

    // LN2
    ln_kernel<<<S, 256>>>(x1, h2, ln2a, ln2b);

    // FFN
    dim3 gFF(FF / GBN, S / GBM);    // (16, 32)
    mma_gemm<1><<<gFF, 256>>>(h2, w1, b1, nullptr, ff, S, FF, D);
    mma_gemm<2><<<gD, 256>>>(ff, w2, b2, x1, out, S, D, FF);
}